// round 8
// baseline (speedup 1.0000x reference)
#include <cuda_runtime.h>
#include <cuda_bf16.h>
#include <math.h>
#include <stdint.h>

#define BB 16
#define SS 2048
#define DD 512
typedef __nv_bfloat16 bf16;

// ---------------------------------------------------------------------------
// Scratch (device globals — no allocation allowed)
// ---------------------------------------------------------------------------
__device__ float g_Wkp[DD * DD];
__device__ float g_Wvp[DD * DD];
__device__ float g_bkp[DD];
__device__ float g_bvp[DD];

__device__ bf16 g_Wq_hi[DD * DD],  g_Wq_lo[DD * DD];
__device__ bf16 g_Wkp_hi[DD * DD], g_Wkp_lo[DD * DD];
__device__ bf16 g_Wvp_hi[DD * DD], g_Wvp_lo[DD * DD];
__device__ bf16 g_Wo_hi[DD * DD],  g_Wo_lo[DD * DD];
__device__ bf16 g_q_hi[(size_t)BB * SS * DD],  g_q_lo[(size_t)BB * SS * DD];
__device__ bf16 g_kp_hi[(size_t)BB * SS * DD], g_kp_lo[(size_t)BB * SS * DD];
__device__ bf16 g_vpT_hi[(size_t)BB * SS * DD], g_vpT_lo[(size_t)BB * SS * DD];
__device__ bf16 g_attn_hi[(size_t)BB * SS * SS], g_attn_lo[(size_t)BB * SS * SS];
__device__ bf16 g_op_hi[(size_t)BB * SS * DD],  g_op_lo[(size_t)BB * SS * DD];

// ---------------------------------------------------------------------------
// helpers
// ---------------------------------------------------------------------------
__device__ __forceinline__ uint32_t smem_u32(const void* p) {
    uint32_t a;
    asm("{ .reg .u64 t; cvta.to.shared.u64 t, %1; cvt.u32.u64 %0, t; }"
        : "=r"(a) : "l"(p));
    return a;
}
__device__ __forceinline__ void cp_async16(uint32_t dst, const void* src) {
    asm volatile("cp.async.cg.shared.global [%0], [%1], 16;"
                 :: "r"(dst), "l"(src) : "memory");
}
__device__ __forceinline__ void cp_commit() {
    asm volatile("cp.async.commit_group;" ::: "memory");
}
__device__ __forceinline__ void cp_wait1() {
    asm volatile("cp.async.wait_group 1;" ::: "memory");
}
__device__ __forceinline__ void cp_wait0() {
    asm volatile("cp.async.wait_group 0;" ::: "memory");
}
__device__ __forceinline__ void ldsm4(uint32_t r[4], uint32_t addr) {
    asm volatile("ldmatrix.sync.aligned.m8n8.x4.shared.b16 {%0,%1,%2,%3}, [%4];"
                 : "=r"(r[0]), "=r"(r[1]), "=r"(r[2]), "=r"(r[3]) : "r"(addr));
}
__device__ __forceinline__ void mma16816(float c[4], const uint32_t a[4],
                                         uint32_t b0, uint32_t b1) {
    asm volatile(
        "mma.sync.aligned.m16n8k16.row.col.f32.bf16.bf16.f32 "
        "{%0,%1,%2,%3}, {%4,%5,%6,%7}, {%8,%9}, {%0,%1,%2,%3};"
        : "+f"(c[0]), "+f"(c[1]), "+f"(c[2]), "+f"(c[3])
        : "r"(a[0]), "r"(a[1]), "r"(a[2]), "r"(a[3]), "r"(b0), "r"(b1));
}
__device__ __forceinline__ void split8(const float4 x, const float4 y,
                                       uint4& hi, uint4& lo) {
    float f[8] = {x.x, x.y, x.z, x.w, y.x, y.y, y.z, y.w};
    uint32_t h[4], l[4];
#pragma unroll
    for (int i = 0; i < 4; i++) {
        __nv_bfloat162 hh = __floats2bfloat162_rn(f[2 * i], f[2 * i + 1]);
        h[i] = *reinterpret_cast<uint32_t*>(&hh);
        float r0 = f[2 * i]     - __bfloat162float(hh.x);
        float r1 = f[2 * i + 1] - __bfloat162float(hh.y);
        __nv_bfloat162 ll = __floats2bfloat162_rn(r0, r1);
        l[i] = *reinterpret_cast<uint32_t*>(&ll);
    }
    hi = make_uint4(h[0], h[1], h[2], h[3]);
    lo = make_uint4(l[0], l[1], l[2], l[3]);
}

// shared compute body: 32-K chunk, all 12 LDSM hoisted, then 48 MMAs
__device__ __forceinline__ void compute_chunk(
    uint32_t ah, uint32_t al, uint32_t bhb, uint32_t blb,
    const uint32_t aoff[4][2], const uint32_t boff[2][2], float c[4][4][4])
{
#pragma unroll
    for (int ks = 0; ks < 2; ks++) {
        uint32_t a[4][4], l[4][4], bh[2][4], bl[2][4];
#pragma unroll
        for (int i = 0; i < 4; i++) ldsm4(a[i], ah + aoff[i][ks]);
#pragma unroll
        for (int j = 0; j < 2; j++) ldsm4(bh[j], bhb + boff[j][ks]);
#pragma unroll
        for (int j = 0; j < 2; j++) ldsm4(bl[j], blb + boff[j][ks]);
#pragma unroll
        for (int i = 0; i < 4; i++) ldsm4(l[i], al + aoff[i][ks]);
#pragma unroll
        for (int i = 0; i < 4; i++)
#pragma unroll
            for (int j = 0; j < 4; j++)
                mma16816(c[i][j], a[i], bh[j >> 1][(j & 1) * 2], bh[j >> 1][(j & 1) * 2 + 1]);
#pragma unroll
        for (int i = 0; i < 4; i++)
#pragma unroll
            for (int j = 0; j < 4; j++)
                mma16816(c[i][j], l[i], bh[j >> 1][(j & 1) * 2], bh[j >> 1][(j & 1) * 2 + 1]);
#pragma unroll
        for (int i = 0; i < 4; i++)
#pragma unroll
            for (int j = 0; j < 4; j++)
                mma16816(c[i][j], a[i], bl[j >> 1][(j & 1) * 2], bl[j >> 1][(j & 1) * 2 + 1]);
    }
}

#define TG_THREADS 256
#define TG_STAGE   32768
#define TG_SMEM    (3 * TG_STAGE)      // 98304: 3 stages; epilogue reuses

// ---------------------------------------------------------------------------
// Pair-input GEMM (A,B hi/lo bf16), 3-stage cp.async, 1 barrier per chunk.
// ---------------------------------------------------------------------------
__global__ __launch_bounds__(TG_THREADS, 2)
void tgemm_kernel(const bf16* __restrict__ Ahi, const bf16* __restrict__ Alo,
                  const bf16* __restrict__ Bhi, const bf16* __restrict__ Blo,
                  float* outF, bf16* outHi, bf16* outLo,
                  const float* __restrict__ bias,
                  int M, int N, int K, float alpha,
                  long long sA, long long sB, long long sC)
{
    extern __shared__ char smem[];
    const uint32_t sb = smem_u32(smem);
    const int tid  = threadIdx.x;
    const int lane = tid & 31;
    const int wid  = tid >> 5;
    const int m0   = (wid & 1) * 64;
    const int n0   = (wid >> 1) * 32;

    const long long bz = blockIdx.z;
    Ahi += bz * sA; Alo += bz * sA;
    Bhi += bz * sB; Blo += bz * sB;
    if (outF)  outF  += bz * sC;
    if (outHi) { outHi += bz * sC; outLo += bz * sC; }

    const int rowBase = blockIdx.y * 128;
    const int colBase = blockIdx.x * 128;

    int ldRow[2], ldK16[2];
    uint32_t ldOff[2];
#pragma unroll
    for (int i = 0; i < 2; i++) {
        int chunk = tid + i * 256;
        ldRow[i] = chunk >> 2;
        ldK16[i] = chunk & 3;
        ldOff[i] = (uint32_t)(ldRow[i] * 64 +
                   ((ldK16[i] ^ ((ldRow[i] >> 1) & 3)) * 16));
    }

    uint32_t aoff[4][2], boff[2][2];
#pragma unroll
    for (int i = 0; i < 4; i++)
#pragma unroll
        for (int ks = 0; ks < 2; ks++) {
            int r = m0 + i * 16 + (lane & 7) + ((lane >> 3) & 1) * 8;
            int ch = ks * 2 + (lane >> 4);
            aoff[i][ks] = (uint32_t)(r * 64 + ((ch ^ ((r >> 1) & 3)) * 16));
        }
#pragma unroll
    for (int j = 0; j < 2; j++)
#pragma unroll
        for (int ks = 0; ks < 2; ks++) {
            int r = n0 + j * 16 + (lane & 7) + ((lane >> 4) & 1) * 8;
            int ch = ks * 2 + ((lane >> 3) & 1);
            boff[j][ks] = (uint32_t)(r * 64 + ((ch ^ ((r >> 1) & 3)) * 16));
        }

    float c[4][4][4];
#pragma unroll
    for (int i = 0; i < 4; i++)
#pragma unroll
        for (int j = 0; j < 4; j++)
#pragma unroll
            for (int e = 0; e < 4; e++) c[i][j][e] = 0.0f;

    const int nc = K >> 5;

    auto load_stage = [&](int cidx) {
        const uint32_t dst = sb + (uint32_t)(cidx % 3) * TG_STAGE;
        const long long kb = (long long)cidx * 32;
#pragma unroll
        for (int i = 0; i < 2; i++) {
            const long long ea = (long long)(rowBase + ldRow[i]) * K + kb + ldK16[i] * 8;
            const long long eb = (long long)(colBase + ldRow[i]) * K + kb + ldK16[i] * 8;
            cp_async16(dst +         ldOff[i], Ahi + ea);
            cp_async16(dst +  8192 + ldOff[i], Alo + ea);
            cp_async16(dst + 16384 + ldOff[i], Bhi + eb);
            cp_async16(dst + 24576 + ldOff[i], Blo + eb);
        }
        cp_commit();
    };

    load_stage(0);
    if (nc > 1) load_stage(1);

    for (int cidx = 0; cidx < nc; cidx++) {
        if (cidx + 1 < nc) cp_wait1(); else cp_wait0();
        __syncthreads();
        if (cidx + 2 < nc) load_stage(cidx + 2);
        const uint32_t st = sb + (uint32_t)(cidx % 3) * TG_STAGE;
        compute_chunk(st, st + 8192, st + 16384, st + 24576, aoff, boff, c);
    }
    __syncthreads();

    // epilogue: regs -> SMEM (pitch 136) -> coalesced gmem
    float* sf = (float*)smem;
#pragma unroll
    for (int i = 0; i < 4; i++) {
        const int r = m0 + i * 16 + (lane >> 2);
#pragma unroll
        for (int j = 0; j < 4; j++) {
            const int cc = n0 + j * 8 + (lane & 3) * 2;
            sf[r * 136 + cc]           = c[i][j][0];
            sf[r * 136 + cc + 1]       = c[i][j][1];
            sf[(r + 8) * 136 + cc]     = c[i][j][2];
            sf[(r + 8) * 136 + cc + 1] = c[i][j][3];
        }
    }
    __syncthreads();
#pragma unroll 4
    for (int e = tid; e < 128 * 128; e += TG_THREADS) {
        const int r = e >> 7, cc = e & 127;
        float v = sf[r * 136 + cc] * alpha;
        const int gc = colBase + cc;
        if (bias) v += bias[gc];
        const long long gi = (long long)(rowBase + r) * N + gc;
        if (outF) outF[gi] = v;
        if (outHi) {
            bf16 h = __float2bfloat16_rn(v);
            outHi[gi] = h;
            outLo[gi] = __float2bfloat16_rn(v - __bfloat162float(h));
        }
    }
}

// ---------------------------------------------------------------------------
// Merged projection GEMM (z = 0:q, 1:k, 2:v). A fp32 split in-kernel;
// B pre-split hi/lo. 3-stage, 1 barrier/chunk. z=2 writes transposed (vpT).
// ---------------------------------------------------------------------------
struct ProjArgs {
    const float* A[3];
    const bf16*  Bh[3];
    const bf16*  Bl[3];
    bf16*        oh[3];
    bf16*        ol[3];
    const float* bias[3];
    int          trans[3];
};

__global__ __launch_bounds__(TG_THREADS, 2)
void tgemm_proj_kernel(ProjArgs pa, int M, int N, int K)
{
    extern __shared__ char smem[];
    const uint32_t sb = smem_u32(smem);
    const int tid  = threadIdx.x;
    const int lane = tid & 31;
    const int wid  = tid >> 5;
    const int m0   = (wid & 1) * 64;
    const int n0   = (wid >> 1) * 32;
    const int z    = blockIdx.z;

    const float* A   = pa.A[z];
    const bf16* Bhi  = pa.Bh[z];
    const bf16* Blo  = pa.Bl[z];
    bf16* outHi      = pa.oh[z];
    bf16* outLo      = pa.ol[z];
    const float* bias = pa.bias[z];
    const int transOut = pa.trans[z];

    const int rowBase = blockIdx.y * 128;
    const int colBase = blockIdx.x * 128;

    int aRow[2], aC8[2];
    uint32_t aSw[2];
#pragma unroll
    for (int i = 0; i < 2; i++) {
        int u = tid + i * 256;
        aRow[i] = u >> 2;
        aC8[i]  = u & 3;
        aSw[i]  = (uint32_t)(aRow[i] * 64 + ((aC8[i] ^ ((aRow[i] >> 1) & 3)) * 16));
    }
    int ldRow[2], ldK16[2];
    uint32_t ldOff[2];
#pragma unroll
    for (int i = 0; i < 2; i++) {
        int chunk = tid + i * 256;
        ldRow[i] = chunk >> 2;
        ldK16[i] = chunk & 3;
        ldOff[i] = (uint32_t)(ldRow[i] * 64 +
                   ((ldK16[i] ^ ((ldRow[i] >> 1) & 3)) * 16));
    }

    uint32_t aoff[4][2], boff[2][2];
#pragma unroll
    for (int i = 0; i < 4; i++)
#pragma unroll
        for (int ks = 0; ks < 2; ks++) {
            int r = m0 + i * 16 + (lane & 7) + ((lane >> 3) & 1) * 8;
            int ch = ks * 2 + (lane >> 4);
            aoff[i][ks] = (uint32_t)(r * 64 + ((ch ^ ((r >> 1) & 3)) * 16));
        }
#pragma unroll
    for (int j = 0; j < 2; j++)
#pragma unroll
        for (int ks = 0; ks < 2; ks++) {
            int r = n0 + j * 16 + (lane & 7) + ((lane >> 4) & 1) * 8;
            int ch = ks * 2 + ((lane >> 3) & 1);
            boff[j][ks] = (uint32_t)(r * 64 + ((ch ^ ((r >> 1) & 3)) * 16));
        }

    float c[4][4][4];
#pragma unroll
    for (int i = 0; i < 4; i++)
#pragma unroll
        for (int j = 0; j < 4; j++)
#pragma unroll
            for (int e = 0; e < 4; e++) c[i][j][e] = 0.0f;

    const int nc = K >> 5;

    auto issueB = [&](int cidx) {
        const uint32_t dst = sb + 49152u + (uint32_t)(cidx % 3) * 16384u;
        const long long kb = (long long)cidx * 32;
#pragma unroll
        for (int i = 0; i < 2; i++) {
            const long long eb = (long long)(colBase + ldRow[i]) * K + kb + ldK16[i] * 8;
            cp_async16(dst +        ldOff[i], Bhi + eb);
            cp_async16(dst + 8192 + ldOff[i], Blo + eb);
        }
        cp_commit();
    };
    auto ldgA = [&](int cidx, float4 ar[2][2]) {
        const long long kb = (long long)cidx * 32;
#pragma unroll
        for (int i = 0; i < 2; i++) {
            const float* p = A + (long long)(rowBase + aRow[i]) * K + kb + aC8[i] * 8;
            ar[i][0] = *(const float4*)(p);
            ar[i][1] = *(const float4*)(p + 4);
        }
    };
    auto stsA = [&](int cidx, const float4 ar[2][2]) {
        char* base = smem + (cidx % 3) * 16384;
#pragma unroll
        for (int i = 0; i < 2; i++) {
            uint4 hi, lo;
            split8(ar[i][0], ar[i][1], hi, lo);
            *(uint4*)(base +        aSw[i]) = hi;
            *(uint4*)(base + 8192 + aSw[i]) = lo;
        }
    };

    float4 ar[2][2];
    ldgA(0, ar);
    issueB(0);
    if (nc > 1) issueB(1);
    stsA(0, ar);
    if (nc > 1) ldgA(1, ar);

    for (int cidx = 0; cidx < nc; cidx++) {
        if (cidx + 1 < nc) cp_wait1(); else cp_wait0();
        __syncthreads();
        if (cidx + 2 < nc) issueB(cidx + 2);
        if (cidx + 1 < nc) stsA(cidx + 1, ar);
        if (cidx + 2 < nc) ldgA(cidx + 2, ar);
        const uint32_t stA = sb + (uint32_t)(cidx % 3) * 16384u;
        const uint32_t stB = sb + 49152u + (uint32_t)(cidx % 3) * 16384u;
        compute_chunk(stA, stA + 8192, stB, stB + 8192, aoff, boff, c);
    }
    __syncthreads();

    // epilogue
    float* sf = (float*)smem;
#pragma unroll
    for (int i = 0; i < 4; i++) {
        const int r = m0 + i * 16 + (lane >> 2);
#pragma unroll
        for (int j = 0; j < 4; j++) {
            const int cc = n0 + j * 8 + (lane & 3) * 2;
            sf[r * 136 + cc]           = c[i][j][0];
            sf[r * 136 + cc + 1]       = c[i][j][1];
            sf[(r + 8) * 136 + cc]     = c[i][j][2];
            sf[(r + 8) * 136 + cc + 1] = c[i][j][3];
        }
    }
    __syncthreads();
#pragma unroll 4
    for (int e = tid; e < 128 * 128; e += TG_THREADS) {
        int r, cc;
        if (transOut) { r = e & 127; cc = e >> 7; }
        else          { r = e >> 7;  cc = e & 127; }
        float v = sf[r * 136 + cc] + bias[colBase + cc];
        long long gi;
        if (transOut) {
            const int grow = rowBase + r;
            gi = (long long)(grow >> 11) * ((long long)DD * SS)
               + (long long)(colBase + cc) * SS + (grow & 2047);
        } else {
            gi = (long long)(rowBase + r) * N + colBase + cc;
        }
        bf16 h = __float2bfloat16_rn(v);
        outHi[gi] = h;
        outLo[gi] = __float2bfloat16_rn(v - __bfloat162float(h));
    }
}

// ---------------------------------------------------------------------------
// fp32 SGEMM (small 512^3 fold GEMMs only): C = A @ B
// ---------------------------------------------------------------------------
__global__ __launch_bounds__(256)
void sgemm_nn_kernel(const float* __restrict__ A, const float* __restrict__ Bm,
                     float* __restrict__ C, int M, int N, int K)
{
    const int BK = 8;
    __shared__ float As[BK][128];
    __shared__ float Bs[BK][128];
    const int tid = threadIdx.x;
    const int tx = tid & 15, ty = tid >> 4;
    const int rowBase = blockIdx.y * 128, colBase = blockIdx.x * 128;
    float acc[8][8];
#pragma unroll
    for (int i = 0; i < 8; i++)
#pragma unroll
        for (int j = 0; j < 8; j++) acc[i][j] = 0.0f;

    for (int k0 = 0; k0 < K; k0 += BK) {
        {
            const int r = tid >> 1, kc = (tid & 1) * 4;
            float4 a = *reinterpret_cast<const float4*>(A + (long long)(rowBase + r) * K + k0 + kc);
            As[kc + 0][r] = a.x; As[kc + 1][r] = a.y; As[kc + 2][r] = a.z; As[kc + 3][r] = a.w;
        }
        {
            const int kr = tid >> 5, ccc = (tid & 31) * 4;
            float4 b = *reinterpret_cast<const float4*>(Bm + (long long)(k0 + kr) * N + colBase + ccc);
            Bs[kr][ccc + 0] = b.x; Bs[kr][ccc + 1] = b.y; Bs[kr][ccc + 2] = b.z; Bs[kr][ccc + 3] = b.w;
        }
        __syncthreads();
#pragma unroll
        for (int k = 0; k < BK; k++) {
            float4 a0 = *reinterpret_cast<const float4*>(&As[k][ty * 8]);
            float4 a1 = *reinterpret_cast<const float4*>(&As[k][ty * 8 + 4]);
            float4 b0 = *reinterpret_cast<const float4*>(&Bs[k][tx * 8]);
            float4 b1 = *reinterpret_cast<const float4*>(&Bs[k][tx * 8 + 4]);
            float arr[8] = {a0.x, a0.y, a0.z, a0.w, a1.x, a1.y, a1.z, a1.w};
            float brr[8] = {b0.x, b0.y, b0.z, b0.w, b1.x, b1.y, b1.z, b1.w};
#pragma unroll
            for (int i = 0; i < 8; i++)
#pragma unroll
                for (int j = 0; j < 8; j++) acc[i][j] = fmaf(arr[i], brr[j], acc[i][j]);
        }
        __syncthreads();
    }
#pragma unroll
    for (int i = 0; i < 8; i++) {
        const int r = rowBase + ty * 8 + i;
#pragma unroll
        for (int j = 0; j < 8; j += 4) {
            const int cc = colBase + tx * 8 + j;
            float4 v = {acc[i][j], acc[i][j + 1], acc[i][j + 2], acc[i][j + 3]};
            *reinterpret_cast<float4*>(C + (long long)r * N + cc) = v;
        }
    }
}

// merged: y=0 -> bkp = E1@bk ; y=1 -> bvp = E2@bv
__global__ void fuse_bias2_kernel(const float* __restrict__ E1,
                                  const float* __restrict__ E2,
                                  const float* __restrict__ bk,
                                  const float* __restrict__ bv,
                                  float* __restrict__ o1,
                                  float* __restrict__ o2)
{
    __shared__ float red[8];
    const float* E = blockIdx.y ? E2 : E1;
    const float* b = blockIdx.y ? bv : bk;
    float* o       = blockIdx.y ? o2 : o1;
    const int p = blockIdx.x;
    float s = 0.0f;
    for (int d = threadIdx.x; d < DD; d += 256)
        s = fmaf(E[(long long)p * DD + d], b[d], s);
#pragma unroll
    for (int off = 16; off > 0; off >>= 1) s += __shfl_xor_sync(0xffffffffu, s, off);
    if ((threadIdx.x & 31) == 0) red[threadIdx.x >> 5] = s;
    __syncthreads();
    if (threadIdx.x == 0) {
        float t = 0.0f;
#pragma unroll
        for (int i = 0; i < 8; i++) t += red[i];
        o[p] = t;
    }
}

// merged weight split: z selects one of 4 (Wq, Wkp, Wvp, Wo)
struct Split4Args {
    const float* src[4];
    bf16* hi[4];
    bf16* lo[4];
};
__global__ void split4_kernel(Split4Args sa)
{
    const int z = blockIdx.z;
    const float* x = sa.src[z];
    bf16* hi = sa.hi[z];
    bf16* lo = sa.lo[z];
    const int n = DD * DD;
    for (int i = blockIdx.x * blockDim.x + threadIdx.x; i < n;
         i += gridDim.x * blockDim.x) {
        float v = x[i];
        bf16 h = __float2bfloat16_rn(v);
        hi[i] = h;
        lo[i] = __float2bfloat16_rn(v - __bfloat162float(h));
    }
}

__global__ __launch_bounds__(256)
void softmax2048_kernel(float* __restrict__ data,
                        bf16* __restrict__ ohi, bf16* __restrict__ olo)
{
    const size_t base = (size_t)blockIdx.x * 2048;
    float* row = data + base;
    const int tid = threadIdx.x;
    __shared__ float red[8];

    float v[8];
    float m = -3.4e38f;
#pragma unroll
    for (int i = 0; i < 8; i++) { v[i] = row[tid + 256 * i]; m = fmaxf(m, v[i]); }
#pragma unroll
    for (int o = 16; o > 0; o >>= 1) m = fmaxf(m, __shfl_xor_sync(0xffffffffu, m, o));
    if ((tid & 31) == 0) red[tid >> 5] = m;
    __syncthreads();
    float bm = red[0];
#pragma unroll
    for (int i = 1; i < 8; i++) bm = fmaxf(bm, red[i]);
    __syncthreads();

    float s = 0.0f;
#pragma unroll
    for (int i = 0; i < 8; i++) { v[i] = __expf(v[i] - bm); s += v[i]; }
#pragma unroll
    for (int o = 16; o > 0; o >>= 1) s += __shfl_xor_sync(0xffffffffu, s, o);
    if ((tid & 31) == 0) red[tid >> 5] = s;
    __syncthreads();
    float bs = 0.0f;
#pragma unroll
    for (int i = 0; i < 8; i++) bs += red[i];

    const float inv = 1.0f / bs;
#pragma unroll
    for (int i = 0; i < 8; i++) {
        float r = v[i] * inv;
        const size_t idx = base + tid + 256 * i;
        data[idx] = r;
        bf16 h = __float2bfloat16_rn(r);
        ohi[idx] = h;
        olo[idx] = __float2bfloat16_rn(r - __bfloat162float(h));
    }
}

// ---------------------------------------------------------------------------
// Launch
// ---------------------------------------------------------------------------
extern "C" void kernel_launch(void* const* d_in, const int* in_sizes, int n_in,
                              void* d_out, int out_size)
{
    const float* q_in = (const float*)d_in[0];
    const float* k_in = (const float*)d_in[1];
    const float* v_in = (const float*)d_in[2];
    const float* Wq   = (const float*)d_in[3];
    const float* bq   = (const float*)d_in[4];
    const float* Wk   = (const float*)d_in[5];
    const float* bk   = (const float*)d_in[6];
    const float* Wv   = (const float*)d_in[7];
    const float* bv   = (const float*)d_in[8];
    const float* E1   = (const float*)d_in[9];
    const float* E2   = (const float*)d_in[10];
    const float* Wo   = (const float*)d_in[11];
    const float* bo   = (const float*)d_in[12];

    float* outp = (float*)d_out;
    float* attn = outp + (size_t)BB * SS * DD;

    float *p_Wkp, *p_Wvp, *p_bkp, *p_bvp;
    cudaGetSymbolAddress((void**)&p_Wkp, g_Wkp);
    cudaGetSymbolAddress((void**)&p_Wvp, g_Wvp);
    cudaGetSymbolAddress((void**)&p_bkp, g_bkp);
    cudaGetSymbolAddress((void**)&p_bvp, g_bvp);
    bf16 *wq_h, *wq_l, *wkp_h, *wkp_l, *wvp_h, *wvp_l, *wo_h, *wo_l;
    bf16 *q_h, *q_l, *kp_h, *kp_l, *vpT_h, *vpT_l, *at_h, *at_l, *op_h, *op_l;
    cudaGetSymbolAddress((void**)&wq_h,  g_Wq_hi);  cudaGetSymbolAddress((void**)&wq_l,  g_Wq_lo);
    cudaGetSymbolAddress((void**)&wkp_h, g_Wkp_hi); cudaGetSymbolAddress((void**)&wkp_l, g_Wkp_lo);
    cudaGetSymbolAddress((void**)&wvp_h, g_Wvp_hi); cudaGetSymbolAddress((void**)&wvp_l, g_Wvp_lo);
    cudaGetSymbolAddress((void**)&wo_h,  g_Wo_hi);  cudaGetSymbolAddress((void**)&wo_l,  g_Wo_lo);
    cudaGetSymbolAddress((void**)&q_h,   g_q_hi);   cudaGetSymbolAddress((void**)&q_l,   g_q_lo);
    cudaGetSymbolAddress((void**)&kp_h,  g_kp_hi);  cudaGetSymbolAddress((void**)&kp_l,  g_kp_lo);
    cudaGetSymbolAddress((void**)&vpT_h, g_vpT_hi); cudaGetSymbolAddress((void**)&vpT_l, g_vpT_lo);
    cudaGetSymbolAddress((void**)&at_h,  g_attn_hi);cudaGetSymbolAddress((void**)&at_l,  g_attn_lo);
    cudaGetSymbolAddress((void**)&op_h,  g_op_hi);  cudaGetSymbolAddress((void**)&op_l,  g_op_lo);

    cudaFuncSetAttribute(tgemm_kernel, cudaFuncAttributeMaxDynamicSharedMemorySize, TG_SMEM);
    cudaFuncSetAttribute(tgemm_proj_kernel, cudaFuncAttributeMaxDynamicSharedMemorySize, TG_SMEM);

    const int M = BB * SS;
    const float scaling = 1.0f / sqrtf((float)DD);
    const dim3 gFold(DD / 128, DD / 128, 1);

    // 0,1: fold GEMMs
    sgemm_nn_kernel<<<gFold, 256>>>(E1, Wk, p_Wkp, DD, DD, DD);
    sgemm_nn_kernel<<<gFold, 256>>>(E2, Wv, p_Wvp, DD, DD, DD);
    // 2: folded biases
    fuse_bias2_kernel<<<dim3(DD, 2), 256>>>(E1, E2, bk, bv, p_bkp, p_bvp);
    // 3: all 4 weight splits
    {
        Split4Args sa;
        sa.src[0] = Wq;    sa.hi[0] = wq_h;  sa.lo[0] = wq_l;
        sa.src[1] = p_Wkp; sa.hi[1] = wkp_h; sa.lo[1] = wkp_l;
        sa.src[2] = p_Wvp; sa.hi[2] = wvp_h; sa.lo[2] = wvp_l;
        sa.src[3] = Wo;    sa.hi[3] = wo_h;  sa.lo[3] = wo_l;
        split4_kernel<<<dim3(128, 1, 4), 256>>>(sa);
    }
    // 4: merged q/k/v projections (grid.z = 3)
    {
        ProjArgs pa;
        pa.A[0] = q_in; pa.Bh[0] = wq_h;  pa.Bl[0] = wq_l;  pa.oh[0] = q_h;   pa.ol[0] = q_l;   pa.bias[0] = bq;    pa.trans[0] = 0;
        pa.A[1] = k_in; pa.Bh[1] = wkp_h; pa.Bl[1] = wkp_l; pa.oh[1] = kp_h;  pa.ol[1] = kp_l;  pa.bias[1] = p_bkp; pa.trans[1] = 0;
        pa.A[2] = v_in; pa.Bh[2] = wvp_h; pa.Bl[2] = wvp_l; pa.oh[2] = vpT_h; pa.ol[2] = vpT_l; pa.bias[2] = p_bvp; pa.trans[2] = 1;
        tgemm_proj_kernel<<<dim3(DD / 128, M / 128, 3), TG_THREADS, TG_SMEM>>>(pa, M, DD, DD);
    }
    // 5: scores = scaling * q @ kp^T -> attn region fp32  (ncu capture target)
    tgemm_kernel<<<dim3(SS / 128, SS / 128, BB), TG_THREADS, TG_SMEM>>>(
        q_h, q_l, kp_h, kp_l, attn, nullptr, nullptr, nullptr,
        SS, SS, DD, scaling,
        (long long)SS * DD, (long long)SS * DD, (long long)SS * SS);
    // 6: softmax in place + hi/lo
    softmax2048_kernel<<<BB * SS, 256>>>(attn, at_h, at_l);
    // 7: op = attn @ vpT^T (K = 2048)
    tgemm_kernel<<<dim3(DD / 128, SS / 128, BB), TG_THREADS, TG_SMEM>>>(
        at_h, at_l, vpT_h, vpT_l, nullptr, op_h, op_l, nullptr,
        SS, DD, SS, 1.0f,
        (long long)SS * SS, (long long)SS * DD, (long long)SS * DD);
    // 8: out = op @ Wo^T + bo
    tgemm_kernel<<<dim3(DD / 128, M / 128, 1), TG_THREADS, TG_SMEM>>>(
        op_h, op_l, wo_h, wo_l, outp, nullptr, nullptr, bo,
        M, DD, DD, 1.0f, 0, 0, 0);
}

// round 9
// speedup vs baseline: 1.2794x; 1.2794x over previous
#include <cuda_runtime.h>
#include <cuda_bf16.h>
#include <math.h>
#include <stdint.h>

#define BB 16
#define SS 2048
#define DD 512

// ---------------------------------------------------------------------------
// Scratch (device globals — no allocation allowed). All GEMM operands are
// fp32 whose bit patterns are already rna-rounded to tf32 precision.
// ---------------------------------------------------------------------------
__device__ float g_Wkp[DD * DD];         // E1 @ Wk (exact fp32)
__device__ float g_Wvp[DD * DD];         // E2 @ Wv
__device__ float g_bkp[DD];
__device__ float g_bvp[DD];
__device__ float g_Wq_t[DD * DD];        // tf32-rounded weights
__device__ float g_Wkp_t[DD * DD];
__device__ float g_Wvp_t[DD * DD];
__device__ float g_Wo_t[DD * DD];
__device__ float g_q[(size_t)BB * SS * DD];     // tf32-rounded activations
__device__ float g_kp[(size_t)BB * SS * DD];
__device__ float g_vpT[(size_t)BB * SS * DD];   // [b][d][t]
__device__ float g_op[(size_t)BB * SS * DD];
__device__ float g_attn_t[(size_t)BB * SS * SS]; // tf32-rounded attn copy

// ---------------------------------------------------------------------------
// helpers
// ---------------------------------------------------------------------------
__device__ __forceinline__ uint32_t smem_u32(const void* p) {
    uint32_t a;
    asm("{ .reg .u64 t; cvta.to.shared.u64 t, %1; cvt.u32.u64 %0, t; }"
        : "=r"(a) : "l"(p));
    return a;
}
__device__ __forceinline__ void cp_async16(uint32_t dst, const void* src) {
    asm volatile("cp.async.cg.shared.global [%0], [%1], 16;"
                 :: "r"(dst), "l"(src) : "memory");
}
__device__ __forceinline__ void cp_commit() {
    asm volatile("cp.async.commit_group;" ::: "memory");
}
__device__ __forceinline__ void cp_wait1() {
    asm volatile("cp.async.wait_group 1;" ::: "memory");
}
__device__ __forceinline__ void cp_wait0() {
    asm volatile("cp.async.wait_group 0;" ::: "memory");
}
__device__ __forceinline__ void ldsm4(uint32_t r[4], uint32_t addr) {
    asm volatile("ldmatrix.sync.aligned.m8n8.x4.shared.b16 {%0,%1,%2,%3}, [%4];"
                 : "=r"(r[0]), "=r"(r[1]), "=r"(r[2]), "=r"(r[3]) : "r"(addr));
}
// tf32 MMA: D(16x8) += A(16x8) * B(8x8)^T; A 4 regs, B 2 regs
__device__ __forceinline__ void mma_tf32(float c[4], const uint32_t a[4],
                                         uint32_t b0, uint32_t b1) {
    asm volatile(
        "mma.sync.aligned.m16n8k8.row.col.f32.tf32.tf32.f32 "
        "{%0,%1,%2,%3}, {%4,%5,%6,%7}, {%8,%9}, {%0,%1,%2,%3};"
        : "+f"(c[0]), "+f"(c[1]), "+f"(c[2]), "+f"(c[3])
        : "r"(a[0]), "r"(a[1]), "r"(a[2]), "r"(a[3]), "r"(b0), "r"(b1));
}
__device__ __forceinline__ uint32_t f2tf(float f) {
    uint32_t u;
    asm("cvt.rna.tf32.f32 %0, %1;" : "=r"(u) : "f"(f));
    return u;
}

// SMEM tile: 128 rows x 128B (32 tf32). swizzle: 16B chunk ch -> ch ^ (row&7)
__device__ __forceinline__ uint32_t tile_off(int row, int ch) {
    return (uint32_t)(row * 128 + ((ch ^ (row & 7)) * 16));
}

// shared compute body: 32-K chunk = 4 k8 steps, 16 MMAs each
__device__ __forceinline__ void compute_chunk_tf32(
    uint32_t stA, uint32_t stB,
    const uint32_t aoff[4][4], const uint32_t boff[2][4], float c[4][4][4])
{
#pragma unroll
    for (int ks = 0; ks < 4; ks++) {
        uint32_t a[4][4], b[2][4];
#pragma unroll
        for (int i = 0; i < 4; i++) ldsm4(a[i], stA + aoff[i][ks]);
#pragma unroll
        for (int j = 0; j < 2; j++) ldsm4(b[j], stB + boff[j][ks]);
#pragma unroll
        for (int i = 0; i < 4; i++)
#pragma unroll
            for (int j = 0; j < 4; j++)
                mma_tf32(c[i][j], a[i], b[j >> 1][(j & 1) * 2], b[j >> 1][(j & 1) * 2 + 1]);
    }
}

// precompute ldsm offset tables (same for all kernels)
__device__ __forceinline__ void make_offsets(int lane, int m0, int n0,
                                             uint32_t aoff[4][4], uint32_t boff[2][4])
{
#pragma unroll
    for (int i = 0; i < 4; i++) {
        const int r = m0 + i * 16 + (lane & 7) + ((lane >> 3) & 1) * 8;
#pragma unroll
        for (int ks = 0; ks < 4; ks++)
            aoff[i][ks] = tile_off(r, ks * 2 + (lane >> 4));
    }
#pragma unroll
    for (int j = 0; j < 2; j++) {
        const int r = n0 + j * 16 + (lane & 7) + ((lane >> 4) & 1) * 8;
#pragma unroll
        for (int ks = 0; ks < 4; ks++)
            boff[j][ks] = tile_off(r, ks * 2 + ((lane >> 3) & 1));
    }
}

#define TG_THREADS 256
#define TG_STAGE   32768              // A 16KB + B 16KB
#define TG_SMEM    (3 * TG_STAGE)     // 98304; epilogue (69632) reuses

// ---------------------------------------------------------------------------
// tf32 GEMM: out = alpha * A @ B^T (+ bias). A,B fp32 (pre-rounded to tf32).
// 128x128 tile, K-chunk 32, 3-stage cp.async, 8 warps (64x32 warp tile).
// roundOut: write tf32-rounded fp32 (for GEMM-input consumers).
// ---------------------------------------------------------------------------
__global__ __launch_bounds__(TG_THREADS, 2)
void tgemm_tf32_kernel(const float* __restrict__ A, const float* __restrict__ Bm,
                       float* __restrict__ out, const float* __restrict__ bias,
                       int M, int N, int K, float alpha, int roundOut,
                       long long sA, long long sB, long long sC)
{
    extern __shared__ char smem[];
    const uint32_t sb = smem_u32(smem);
    const int tid  = threadIdx.x;
    const int lane = tid & 31;
    const int wid  = tid >> 5;
    const int m0   = (wid & 1) * 64;
    const int n0   = (wid >> 1) * 32;

    const long long bz = blockIdx.z;
    A  += bz * sA;
    Bm += bz * sB;
    out += bz * sC;

    const int rowBase = blockIdx.y * 128;
    const int colBase = blockIdx.x * 128;

    // cp.async geometry: 4 units of 16B per tile per thread
    int ldRow[4], ldCh[4];
    uint32_t ldOff[4];
#pragma unroll
    for (int i = 0; i < 4; i++) {
        const int u = tid + i * 256;       // 0..1023
        ldRow[i] = u >> 3;
        ldCh[i]  = u & 7;
        ldOff[i] = tile_off(ldRow[i], ldCh[i]);
    }

    uint32_t aoff[4][4], boff[2][4];
    make_offsets(lane, m0, n0, aoff, boff);

    float c[4][4][4];
#pragma unroll
    for (int i = 0; i < 4; i++)
#pragma unroll
        for (int j = 0; j < 4; j++)
#pragma unroll
            for (int e = 0; e < 4; e++) c[i][j][e] = 0.0f;

    const int nc = K >> 5;

    auto load_stage = [&](int cidx) {
        const uint32_t dst = sb + (uint32_t)(cidx % 3) * TG_STAGE;
        const long long kb = (long long)cidx * 32;
#pragma unroll
        for (int i = 0; i < 4; i++) {
            const long long ea = (long long)(rowBase + ldRow[i]) * K + kb + ldCh[i] * 4;
            const long long eb = (long long)(colBase + ldRow[i]) * K + kb + ldCh[i] * 4;
            cp_async16(dst +          ldOff[i], A  + ea);
            cp_async16(dst + 16384u + ldOff[i], Bm + eb);
        }
        cp_commit();
    };

    load_stage(0);
    if (nc > 1) load_stage(1);

    for (int cidx = 0; cidx < nc; cidx++) {
        if (cidx + 1 < nc) cp_wait1(); else cp_wait0();
        __syncthreads();
        if (cidx + 2 < nc) load_stage(cidx + 2);
        const uint32_t st = sb + (uint32_t)(cidx % 3) * TG_STAGE;
        compute_chunk_tf32(st, st + 16384u, aoff, boff, c);
    }
    __syncthreads();

    // epilogue: regs -> SMEM (pitch 136) -> coalesced gmem
    float* sf = (float*)smem;
#pragma unroll
    for (int i = 0; i < 4; i++) {
        const int r = m0 + i * 16 + (lane >> 2);
#pragma unroll
        for (int j = 0; j < 4; j++) {
            const int cc = n0 + j * 8 + (lane & 3) * 2;
            sf[r * 136 + cc]           = c[i][j][0];
            sf[r * 136 + cc + 1]       = c[i][j][1];
            sf[(r + 8) * 136 + cc]     = c[i][j][2];
            sf[(r + 8) * 136 + cc + 1] = c[i][j][3];
        }
    }
    __syncthreads();
#pragma unroll 4
    for (int e = tid; e < 128 * 128; e += TG_THREADS) {
        const int r = e >> 7, cc = e & 127;
        float v = sf[r * 136 + cc] * alpha;
        const int gc = colBase + cc;
        if (bias) v += bias[gc];
        if (roundOut) v = __uint_as_float(f2tf(v));
        out[(long long)(rowBase + r) * N + gc] = v;
    }
}

// ---------------------------------------------------------------------------
// Merged projection GEMM (z = 0:q, 1:k, 2:v). A raw fp32 inputs (rounded to
// tf32 during STS); B pre-rounded weights via cp.async. z=2 writes vpT.
// Output always tf32-rounded fp32 (+bias first).
// ---------------------------------------------------------------------------
struct ProjArgs {
    const float* A[3];
    const float* Bt[3];
    float*       out[3];
    const float* bias[3];
    int          trans[3];
};

__global__ __launch_bounds__(TG_THREADS, 2)
void tgemm_proj_kernel(ProjArgs pa, int M, int N, int K)
{
    extern __shared__ char smem[];
    const uint32_t sb = smem_u32(smem);
    const int tid  = threadIdx.x;
    const int lane = tid & 31;
    const int wid  = tid >> 5;
    const int m0   = (wid & 1) * 64;
    const int n0   = (wid >> 1) * 32;
    const int z    = blockIdx.z;

    const float* A    = pa.A[z];
    const float* Bt   = pa.Bt[z];
    float* out        = pa.out[z];
    const float* bias = pa.bias[z];
    const int transOut = pa.trans[z];

    const int rowBase = blockIdx.y * 128;
    const int colBase = blockIdx.x * 128;

    int ldRow[4], ldCh[4];
    uint32_t ldOff[4];
#pragma unroll
    for (int i = 0; i < 4; i++) {
        const int u = tid + i * 256;
        ldRow[i] = u >> 3;
        ldCh[i]  = u & 7;
        ldOff[i] = tile_off(ldRow[i], ldCh[i]);
    }

    uint32_t aoff[4][4], boff[2][4];
    make_offsets(lane, m0, n0, aoff, boff);

    float c[4][4][4];
#pragma unroll
    for (int i = 0; i < 4; i++)
#pragma unroll
        for (int j = 0; j < 4; j++)
#pragma unroll
            for (int e = 0; e < 4; e++) c[i][j][e] = 0.0f;

    const int nc = K >> 5;

    auto issueB = [&](int cidx) {
        const uint32_t dst = sb + 16384u + (uint32_t)(cidx % 3) * TG_STAGE;
        const long long kb = (long long)cidx * 32;
#pragma unroll
        for (int i = 0; i < 4; i++) {
            const long long eb = (long long)(colBase + ldRow[i]) * K + kb + ldCh[i] * 4;
            cp_async16(dst + ldOff[i], Bt + eb);
        }
        cp_commit();
    };
    auto ldgA = [&](int cidx, float4 ar[4]) {
        const long long kb = (long long)cidx * 32;
#pragma unroll
        for (int i = 0; i < 4; i++)
            ar[i] = *(const float4*)(A + (long long)(rowBase + ldRow[i]) * K + kb + ldCh[i] * 4);
    };
    auto stsA = [&](int cidx, const float4 ar[4]) {
        char* base = smem + (cidx % 3) * TG_STAGE;
#pragma unroll
        for (int i = 0; i < 4; i++) {
            uint4 t;
            t.x = f2tf(ar[i].x); t.y = f2tf(ar[i].y);
            t.z = f2tf(ar[i].z); t.w = f2tf(ar[i].w);
            *(uint4*)(base + ldOff[i]) = t;
        }
    };

    float4 ar[4];
    ldgA(0, ar);
    issueB(0);
    if (nc > 1) issueB(1);
    stsA(0, ar);
    if (nc > 1) ldgA(1, ar);

    for (int cidx = 0; cidx < nc; cidx++) {
        if (cidx + 1 < nc) cp_wait1(); else cp_wait0();
        __syncthreads();
        if (cidx + 2 < nc) issueB(cidx + 2);
        if (cidx + 1 < nc) stsA(cidx + 1, ar);
        if (cidx + 2 < nc) ldgA(cidx + 2, ar);
        const uint32_t st = sb + (uint32_t)(cidx % 3) * TG_STAGE;
        compute_chunk_tf32(st, st + 16384u, aoff, boff, c);
    }
    __syncthreads();

    // epilogue
    float* sf = (float*)smem;
#pragma unroll
    for (int i = 0; i < 4; i++) {
        const int r = m0 + i * 16 + (lane >> 2);
#pragma unroll
        for (int j = 0; j < 4; j++) {
            const int cc = n0 + j * 8 + (lane & 3) * 2;
            sf[r * 136 + cc]           = c[i][j][0];
            sf[r * 136 + cc + 1]       = c[i][j][1];
            sf[(r + 8) * 136 + cc]     = c[i][j][2];
            sf[(r + 8) * 136 + cc + 1] = c[i][j][3];
        }
    }
    __syncthreads();
#pragma unroll 4
    for (int e = tid; e < 128 * 128; e += TG_THREADS) {
        int r, cc;
        if (transOut) { r = e & 127; cc = e >> 7; }   // r fast => coalesced trans store
        else          { r = e >> 7;  cc = e & 127; }
        float v = sf[r * 136 + cc] + bias[colBase + cc];
        v = __uint_as_float(f2tf(v));
        long long gi;
        if (transOut) {
            const int grow = rowBase + r;
            gi = (long long)(grow >> 11) * ((long long)DD * SS)
               + (long long)(colBase + cc) * SS + (grow & 2047);
        } else {
            gi = (long long)(rowBase + r) * N + colBase + cc;
        }
        out[gi] = v;
    }
}

// ---------------------------------------------------------------------------
// fp32 SGEMM (small 512^3 fold GEMMs only): C = A @ B
// ---------------------------------------------------------------------------
__global__ __launch_bounds__(256)
void sgemm_nn_kernel(const float* __restrict__ A, const float* __restrict__ Bm,
                     float* __restrict__ C, int M, int N, int K)
{
    const int BK = 8;
    __shared__ float As[BK][128];
    __shared__ float Bs[BK][128];
    const int tid = threadIdx.x;
    const int tx = tid & 15, ty = tid >> 4;
    const int rowBase = blockIdx.y * 128, colBase = blockIdx.x * 128;
    float acc[8][8];
#pragma unroll
    for (int i = 0; i < 8; i++)
#pragma unroll
        for (int j = 0; j < 8; j++) acc[i][j] = 0.0f;

    for (int k0 = 0; k0 < K; k0 += BK) {
        {
            const int r = tid >> 1, kc = (tid & 1) * 4;
            float4 a = *reinterpret_cast<const float4*>(A + (long long)(rowBase + r) * K + k0 + kc);
            As[kc + 0][r] = a.x; As[kc + 1][r] = a.y; As[kc + 2][r] = a.z; As[kc + 3][r] = a.w;
        }
        {
            const int kr = tid >> 5, ccc = (tid & 31) * 4;
            float4 b = *reinterpret_cast<const float4*>(Bm + (long long)(k0 + kr) * N + colBase + ccc);
            Bs[kr][ccc + 0] = b.x; Bs[kr][ccc + 1] = b.y; Bs[kr][ccc + 2] = b.z; Bs[kr][ccc + 3] = b.w;
        }
        __syncthreads();
#pragma unroll
        for (int k = 0; k < BK; k++) {
            float4 a0 = *reinterpret_cast<const float4*>(&As[k][ty * 8]);
            float4 a1 = *reinterpret_cast<const float4*>(&As[k][ty * 8 + 4]);
            float4 b0 = *reinterpret_cast<const float4*>(&Bs[k][tx * 8]);
            float4 b1 = *reinterpret_cast<const float4*>(&Bs[k][tx * 8 + 4]);
            float arr[8] = {a0.x, a0.y, a0.z, a0.w, a1.x, a1.y, a1.z, a1.w};
            float brr[8] = {b0.x, b0.y, b0.z, b0.w, b1.x, b1.y, b1.z, b1.w};
#pragma unroll
            for (int i = 0; i < 8; i++)
#pragma unroll
                for (int j = 0; j < 8; j++) acc[i][j] = fmaf(arr[i], brr[j], acc[i][j]);
        }
        __syncthreads();
    }
#pragma unroll
    for (int i = 0; i < 8; i++) {
        const int r = rowBase + ty * 8 + i;
#pragma unroll
        for (int j = 0; j < 8; j += 4) {
            const int cc = colBase + tx * 8 + j;
            float4 v = {acc[i][j], acc[i][j + 1], acc[i][j + 2], acc[i][j + 3]};
            *reinterpret_cast<float4*>(C + (long long)r * N + cc) = v;
        }
    }
}

// merged: y=0 -> bkp = E1@bk ; y=1 -> bvp = E2@bv
__global__ void fuse_bias2_kernel(const float* __restrict__ E1,
                                  const float* __restrict__ E2,
                                  const float* __restrict__ bk,
                                  const float* __restrict__ bv,
                                  float* __restrict__ o1,
                                  float* __restrict__ o2)
{
    __shared__ float red[8];
    const float* E = blockIdx.y ? E2 : E1;
    const float* b = blockIdx.y ? bv : bk;
    float* o       = blockIdx.y ? o2 : o1;
    const int p = blockIdx.x;
    float s = 0.0f;
    for (int d = threadIdx.x; d < DD; d += 256)
        s = fmaf(E[(long long)p * DD + d], b[d], s);
#pragma unroll
    for (int off = 16; off > 0; off >>= 1) s += __shfl_xor_sync(0xffffffffu, s, off);
    if ((threadIdx.x & 31) == 0) red[threadIdx.x >> 5] = s;
    __syncthreads();
    if (threadIdx.x == 0) {
        float t = 0.0f;
#pragma unroll
        for (int i = 0; i < 8; i++) t += red[i];
        o[p] = t;
    }
}

// round 4 weight matrices to tf32-in-fp32
struct Round4Args {
    const float* src[4];
    float* dst[4];
};
__global__ void round4_kernel(Round4Args ra)
{
    const int z = blockIdx.z;
    const float* x = ra.src[z];
    float* y = ra.dst[z];
    const int n = DD * DD;
    for (int i = blockIdx.x * blockDim.x + threadIdx.x; i < n;
         i += gridDim.x * blockDim.x)
        y[i] = __uint_as_float(f2tf(x[i]));
}

// softmax rows of 2048 in place (exact) + tf32-rounded copy
__global__ __launch_bounds__(256)
void softmax2048_kernel(float* __restrict__ data, float* __restrict__ rounded)
{
    const size_t base = (size_t)blockIdx.x * 2048;
    float* row = data + base;
    const int tid = threadIdx.x;
    __shared__ float red[8];

    float v[8];
    float m = -3.4e38f;
#pragma unroll
    for (int i = 0; i < 8; i++) { v[i] = row[tid + 256 * i]; m = fmaxf(m, v[i]); }
#pragma unroll
    for (int o = 16; o > 0; o >>= 1) m = fmaxf(m, __shfl_xor_sync(0xffffffffu, m, o));
    if ((tid & 31) == 0) red[tid >> 5] = m;
    __syncthreads();
    float bm = red[0];
#pragma unroll
    for (int i = 1; i < 8; i++) bm = fmaxf(bm, red[i]);
    __syncthreads();

    float s = 0.0f;
#pragma unroll
    for (int i = 0; i < 8; i++) { v[i] = __expf(v[i] - bm); s += v[i]; }
#pragma unroll
    for (int o = 16; o > 0; o >>= 1) s += __shfl_xor_sync(0xffffffffu, s, o);
    if ((tid & 31) == 0) red[tid >> 5] = s;
    __syncthreads();
    float bs = 0.0f;
#pragma unroll
    for (int i = 0; i < 8; i++) bs += red[i];

    const float inv = 1.0f / bs;
#pragma unroll
    for (int i = 0; i < 8; i++) {
        float r = v[i] * inv;
        const size_t idx = base + tid + 256 * i;
        data[idx] = r;
        rounded[idx] = __uint_as_float(f2tf(r));
    }
}

// ---------------------------------------------------------------------------
// Launch
// ---------------------------------------------------------------------------
extern "C" void kernel_launch(void* const* d_in, const int* in_sizes, int n_in,
                              void* d_out, int out_size)
{
    const float* q_in = (const float*)d_in[0];
    const float* k_in = (const float*)d_in[1];
    const float* v_in = (const float*)d_in[2];
    const float* Wq   = (const float*)d_in[3];
    const float* bq   = (const float*)d_in[4];
    const float* Wk   = (const float*)d_in[5];
    const float* bk   = (const float*)d_in[6];
    const float* Wv   = (const float*)d_in[7];
    const float* bv   = (const float*)d_in[8];
    const float* E1   = (const float*)d_in[9];
    const float* E2   = (const float*)d_in[10];
    const float* Wo   = (const float*)d_in[11];
    const float* bo   = (const float*)d_in[12];

    float* outp = (float*)d_out;
    float* attn = outp + (size_t)BB * SS * DD;

    float *p_Wkp, *p_Wvp, *p_bkp, *p_bvp;
    float *wq_t, *wkp_t, *wvp_t, *wo_t;
    float *p_q, *p_kp, *p_vpT, *p_op, *p_at;
    cudaGetSymbolAddress((void**)&p_Wkp, g_Wkp);
    cudaGetSymbolAddress((void**)&p_Wvp, g_Wvp);
    cudaGetSymbolAddress((void**)&p_bkp, g_bkp);
    cudaGetSymbolAddress((void**)&p_bvp, g_bvp);
    cudaGetSymbolAddress((void**)&wq_t,  g_Wq_t);
    cudaGetSymbolAddress((void**)&wkp_t, g_Wkp_t);
    cudaGetSymbolAddress((void**)&wvp_t, g_Wvp_t);
    cudaGetSymbolAddress((void**)&wo_t,  g_Wo_t);
    cudaGetSymbolAddress((void**)&p_q,   g_q);
    cudaGetSymbolAddress((void**)&p_kp,  g_kp);
    cudaGetSymbolAddress((void**)&p_vpT, g_vpT);
    cudaGetSymbolAddress((void**)&p_op,  g_op);
    cudaGetSymbolAddress((void**)&p_at,  g_attn_t);

    cudaFuncSetAttribute(tgemm_tf32_kernel, cudaFuncAttributeMaxDynamicSharedMemorySize, TG_SMEM);
    cudaFuncSetAttribute(tgemm_proj_kernel, cudaFuncAttributeMaxDynamicSharedMemorySize, TG_SMEM);

    const int M = BB * SS;
    const float scaling = 1.0f / sqrtf((float)DD);
    const dim3 gFold(DD / 128, DD / 128, 1);

    // 0,1: fold GEMMs (fp32 exact)
    sgemm_nn_kernel<<<gFold, 256>>>(E1, Wk, p_Wkp, DD, DD, DD);
    sgemm_nn_kernel<<<gFold, 256>>>(E2, Wv, p_Wvp, DD, DD, DD);
    // 2: folded biases
    fuse_bias2_kernel<<<dim3(DD, 2), 256>>>(E1, E2, bk, bv, p_bkp, p_bvp);
    // 3: round all 4 weight matrices to tf32
    {
        Round4Args ra;
        ra.src[0] = Wq;    ra.dst[0] = wq_t;
        ra.src[1] = p_Wkp; ra.dst[1] = wkp_t;
        ra.src[2] = p_Wvp; ra.dst[2] = wvp_t;
        ra.src[3] = Wo;    ra.dst[3] = wo_t;
        round4_kernel<<<dim3(128, 1, 4), 256>>>(ra);
    }
    // 4: merged q/k/v projections (grid.z = 3); v writes vpT
    {
        ProjArgs pa;
        pa.A[0] = q_in; pa.Bt[0] = wq_t;  pa.out[0] = p_q;   pa.bias[0] = bq;    pa.trans[0] = 0;
        pa.A[1] = k_in; pa.Bt[1] = wkp_t; pa.out[1] = p_kp;  pa.bias[1] = p_bkp; pa.trans[1] = 0;
        pa.A[2] = v_in; pa.Bt[2] = wvp_t; pa.out[2] = p_vpT; pa.bias[2] = p_bvp; pa.trans[2] = 1;
        tgemm_proj_kernel<<<dim3(DD / 128, M / 128, 3), TG_THREADS, TG_SMEM>>>(pa, M, DD, DD);
    }
    // 5: scores = scaling * q @ kp^T -> attn region (exact fp32)  [ncu target]
    tgemm_tf32_kernel<<<dim3(SS / 128, SS / 128, BB), TG_THREADS, TG_SMEM>>>(
        p_q, p_kp, attn, nullptr, SS, SS, DD, scaling, 0,
        (long long)SS * DD, (long long)SS * DD, (long long)SS * SS);
    // 6: softmax in place + rounded copy
    softmax2048_kernel<<<BB * SS, 256>>>(attn, p_at);
    // 7: op = attn @ vpT^T (K = 2048), rounded output
    tgemm_tf32_kernel<<<dim3(DD / 128, SS / 128, BB), TG_THREADS, TG_SMEM>>>(
        p_at, p_vpT, p_op, nullptr, SS, DD, SS, 1.0f, 1,
        (long long)SS * SS, (long long)SS * DD, (long long)SS * DD);
    // 8: out = op @ Wo^T + bo (exact fp32)
    tgemm_tf32_kernel<<<dim3(DD / 128, M / 128, 1), TG_THREADS, TG_SMEM>>>(
        p_op, wo_t, outp, bo, M, DD, DD, 1.0f, 0, 0, 0, 0);
}

// round 10
// speedup vs baseline: 1.7821x; 1.3930x over previous
#include <cuda_runtime.h>
#include <cuda_fp16.h>
#include <math.h>
#include <stdint.h>

#define BB 16
#define SS 2048
#define DD 512

// ---------------------------------------------------------------------------
// Scratch (device globals — no allocation allowed)
// ---------------------------------------------------------------------------
__device__ float g_Wkp[DD * DD];           // E1 @ Wk (exact fp32)
__device__ float g_Wvp[DD * DD];           // E2 @ Wv
__device__ float g_bkp[DD];
__device__ float g_bvp[DD];
__device__ __half g_Wq_h[DD * DD];
__device__ __half g_Wkp_h[DD * DD];
__device__ __half g_Wvp_h[DD * DD];
__device__ __half g_Wo_h[DD * DD];
__device__ __half g_q_h[(size_t)BB * SS * DD];
__device__ __half g_kp_h[(size_t)BB * SS * DD];
__device__ __half g_vpT_h[(size_t)BB * SS * DD];   // [b][d][t]
__device__ __half g_op_h[(size_t)BB * SS * DD];
__device__ __half g_attn_h[(size_t)BB * SS * SS];  // fp16 attn copy

// ---------------------------------------------------------------------------
// helpers
// ---------------------------------------------------------------------------
__device__ __forceinline__ uint32_t smem_u32(const void* p) {
    uint32_t a;
    asm("{ .reg .u64 t; cvta.to.shared.u64 t, %1; cvt.u32.u64 %0, t; }"
        : "=r"(a) : "l"(p));
    return a;
}
__device__ __forceinline__ void cp_async16(uint32_t dst, const void* src) {
    asm volatile("cp.async.cg.shared.global [%0], [%1], 16;"
                 :: "r"(dst), "l"(src) : "memory");
}
__device__ __forceinline__ void cp_commit() {
    asm volatile("cp.async.commit_group;" ::: "memory");
}
__device__ __forceinline__ void cp_wait1() {
    asm volatile("cp.async.wait_group 1;" ::: "memory");
}
__device__ __forceinline__ void cp_wait0() {
    asm volatile("cp.async.wait_group 0;" ::: "memory");
}
__device__ __forceinline__ void ldsm4(uint32_t r[4], uint32_t addr) {
    asm volatile("ldmatrix.sync.aligned.m8n8.x4.shared.b16 {%0,%1,%2,%3}, [%4];"
                 : "=r"(r[0]), "=r"(r[1]), "=r"(r[2]), "=r"(r[3]) : "r"(addr));
}
// fp16 MMA: D(16x8) += A(16x16) * B(8x16)^T, fp32 accumulate
__device__ __forceinline__ void mma_f16(float c[4], const uint32_t a[4],
                                        uint32_t b0, uint32_t b1) {
    asm volatile(
        "mma.sync.aligned.m16n8k16.row.col.f32.f16.f16.f32 "
        "{%0,%1,%2,%3}, {%4,%5,%6,%7}, {%8,%9}, {%0,%1,%2,%3};"
        : "+f"(c[0]), "+f"(c[1]), "+f"(c[2]), "+f"(c[3])
        : "r"(a[0]), "r"(a[1]), "r"(a[2]), "r"(a[3]), "r"(b0), "r"(b1));
}

// SMEM tile: 128 rows x 128B (64 fp16). swizzle: 16B chunk ch -> ch ^ (row&7)
__device__ __forceinline__ uint32_t tile_off(int row, int ch) {
    return (uint32_t)(row * 128 + ((ch ^ (row & 7)) * 16));
}

// 64-K chunk = 4 k16 steps; per step: 4 A-ldsm + 2 B-ldsm + 16 MMA
__device__ __forceinline__ void compute_chunk_f16(
    uint32_t stA, uint32_t stB,
    const uint32_t aoff[4][4], const uint32_t boff[2][4], float c[4][4][4])
{
#pragma unroll
    for (int ks = 0; ks < 4; ks++) {
        uint32_t a[4][4], b[2][4];
#pragma unroll
        for (int i = 0; i < 4; i++) ldsm4(a[i], stA + aoff[i][ks]);
#pragma unroll
        for (int j = 0; j < 2; j++) ldsm4(b[j], stB + boff[j][ks]);
#pragma unroll
        for (int i = 0; i < 4; i++)
#pragma unroll
            for (int j = 0; j < 4; j++)
                mma_f16(c[i][j], a[i], b[j >> 1][(j & 1) * 2], b[j >> 1][(j & 1) * 2 + 1]);
    }
}

__device__ __forceinline__ void make_offsets(int lane, int m0, int n0,
                                             uint32_t aoff[4][4], uint32_t boff[2][4])
{
#pragma unroll
    for (int i = 0; i < 4; i++) {
        const int r = m0 + i * 16 + (lane & 7) + ((lane >> 3) & 1) * 8;
#pragma unroll
        for (int ks = 0; ks < 4; ks++)
            aoff[i][ks] = tile_off(r, ks * 2 + (lane >> 4));
    }
#pragma unroll
    for (int j = 0; j < 2; j++) {
        const int r = n0 + j * 16 + (lane & 7) + ((lane >> 4) & 1) * 8;
#pragma unroll
        for (int ks = 0; ks < 4; ks++)
            boff[j][ks] = tile_off(r, ks * 2 + ((lane >> 3) & 1));
    }
}

#define TG_THREADS 256
#define TG_STAGE   32768              // A 16KB + B 16KB (64-K chunk, fp16)
#define TG_SMEM    (3 * TG_STAGE)     // 98304; epilogue (69632) reuses

// ---------------------------------------------------------------------------
// fp16 GEMM: out = alpha * A @ B^T (+ bias). A,B fp16. 128x128 tile,
// K-chunk 64, 3-stage cp.async, 8 warps (64x32 warp tile), 2 CTA/SM.
// outF: fp32 output; outH: fp16 output (either may be null).
// ---------------------------------------------------------------------------
__global__ __launch_bounds__(TG_THREADS, 2)
void tgemm_f16_kernel(const __half* __restrict__ A, const __half* __restrict__ Bm,
                      float* outF, __half* outH, const float* __restrict__ bias,
                      int M, int N, int K, float alpha,
                      long long sA, long long sB, long long sC)
{
    extern __shared__ char smem[];
    const uint32_t sb = smem_u32(smem);
    const int tid  = threadIdx.x;
    const int lane = tid & 31;
    const int wid  = tid >> 5;
    const int m0   = (wid & 1) * 64;
    const int n0   = (wid >> 1) * 32;

    const long long bz = blockIdx.z;
    A  += bz * sA;
    Bm += bz * sB;
    if (outF) outF += bz * sC;
    if (outH) outH += bz * sC;

    const int rowBase = blockIdx.y * 128;
    const int colBase = blockIdx.x * 128;

    // cp.async geometry: 4 units of 16B (8 fp16) per operand tile per thread
    int ldRow[4], ldCh[4];
    uint32_t ldOff[4];
#pragma unroll
    for (int i = 0; i < 4; i++) {
        const int u = tid + i * 256;
        ldRow[i] = u >> 3;
        ldCh[i]  = u & 7;
        ldOff[i] = tile_off(ldRow[i], ldCh[i]);
    }

    uint32_t aoff[4][4], boff[2][4];
    make_offsets(lane, m0, n0, aoff, boff);

    float c[4][4][4];
#pragma unroll
    for (int i = 0; i < 4; i++)
#pragma unroll
        for (int j = 0; j < 4; j++)
#pragma unroll
            for (int e = 0; e < 4; e++) c[i][j][e] = 0.0f;

    const int nc = K >> 6;

    auto load_stage = [&](int cidx) {
        const uint32_t dst = sb + (uint32_t)(cidx % 3) * TG_STAGE;
        const long long kb = (long long)cidx * 64;
#pragma unroll
        for (int i = 0; i < 4; i++) {
            const long long ea = (long long)(rowBase + ldRow[i]) * K + kb + ldCh[i] * 8;
            const long long eb = (long long)(colBase + ldRow[i]) * K + kb + ldCh[i] * 8;
            cp_async16(dst +          ldOff[i], A  + ea);
            cp_async16(dst + 16384u + ldOff[i], Bm + eb);
        }
        cp_commit();
    };

    load_stage(0);
    if (nc > 1) load_stage(1);

    for (int cidx = 0; cidx < nc; cidx++) {
        if (cidx + 1 < nc) cp_wait1(); else cp_wait0();
        __syncthreads();
        if (cidx + 2 < nc) load_stage(cidx + 2);
        const uint32_t st = sb + (uint32_t)(cidx % 3) * TG_STAGE;
        compute_chunk_f16(st, st + 16384u, aoff, boff, c);
    }
    __syncthreads();

    // epilogue: regs -> SMEM (pitch 136 floats) -> coalesced gmem
    float* sf = (float*)smem;
#pragma unroll
    for (int i = 0; i < 4; i++) {
        const int r = m0 + i * 16 + (lane >> 2);
#pragma unroll
        for (int j = 0; j < 4; j++) {
            const int cc = n0 + j * 8 + (lane & 3) * 2;
            sf[r * 136 + cc]           = c[i][j][0];
            sf[r * 136 + cc + 1]       = c[i][j][1];
            sf[(r + 8) * 136 + cc]     = c[i][j][2];
            sf[(r + 8) * 136 + cc + 1] = c[i][j][3];
        }
    }
    __syncthreads();
#pragma unroll 4
    for (int e = tid; e < 128 * 128; e += TG_THREADS) {
        const int r = e >> 7, cc = e & 127;
        float v = sf[r * 136 + cc] * alpha;
        const int gc = colBase + cc;
        if (bias) v += bias[gc];
        const long long gi = (long long)(rowBase + r) * N + gc;
        if (outF) outF[gi] = v;
        if (outH) outH[gi] = __float2half_rn(v);
    }
}

// ---------------------------------------------------------------------------
// Merged projection GEMM (z = 0:q, 1:k, 2:v). A fp32 (cvt fp16 during STS);
// B fp16 weights via cp.async. Output fp16 (+bias first); z=2 transposed.
// ---------------------------------------------------------------------------
struct ProjArgs {
    const float*  A[3];
    const __half* Bh[3];
    __half*       out[3];
    const float*  bias[3];
    int           trans[3];
};

__global__ __launch_bounds__(TG_THREADS, 2)
void tgemm_proj_kernel(ProjArgs pa, int M, int N, int K)
{
    extern __shared__ char smem[];
    const uint32_t sb = smem_u32(smem);
    const int tid  = threadIdx.x;
    const int lane = tid & 31;
    const int wid  = tid >> 5;
    const int m0   = (wid & 1) * 64;
    const int n0   = (wid >> 1) * 32;
    const int z    = blockIdx.z;

    const float* A    = pa.A[z];
    const __half* Bh  = pa.Bh[z];
    __half* out       = pa.out[z];
    const float* bias = pa.bias[z];
    const int transOut = pa.trans[z];

    const int rowBase = blockIdx.y * 128;
    const int colBase = blockIdx.x * 128;

    int ldRow[4], ldCh[4];
    uint32_t ldOff[4];
#pragma unroll
    for (int i = 0; i < 4; i++) {
        const int u = tid + i * 256;
        ldRow[i] = u >> 3;
        ldCh[i]  = u & 7;
        ldOff[i] = tile_off(ldRow[i], ldCh[i]);
    }

    uint32_t aoff[4][4], boff[2][4];
    make_offsets(lane, m0, n0, aoff, boff);

    float c[4][4][4];
#pragma unroll
    for (int i = 0; i < 4; i++)
#pragma unroll
        for (int j = 0; j < 4; j++)
#pragma unroll
            for (int e = 0; e < 4; e++) c[i][j][e] = 0.0f;

    const int nc = K >> 6;

    auto issueB = [&](int cidx) {
        const uint32_t dst = sb + 16384u + (uint32_t)(cidx % 3) * TG_STAGE;
        const long long kb = (long long)cidx * 64;
#pragma unroll
        for (int i = 0; i < 4; i++) {
            const long long eb = (long long)(colBase + ldRow[i]) * K + kb + ldCh[i] * 8;
            cp_async16(dst + ldOff[i], Bh + eb);
        }
        cp_commit();
    };
    auto ldgA = [&](int cidx, float4 ar[4][2]) {
        const long long kb = (long long)cidx * 64;
#pragma unroll
        for (int i = 0; i < 4; i++) {
            const float* p = A + (long long)(rowBase + ldRow[i]) * K + kb + ldCh[i] * 8;
            ar[i][0] = *(const float4*)(p);
            ar[i][1] = *(const float4*)(p + 4);
        }
    };
    auto stsA = [&](int cidx, const float4 ar[4][2]) {
        char* base = smem + (cidx % 3) * TG_STAGE;
#pragma unroll
        for (int i = 0; i < 4; i++) {
            uint4 t;
            __half2 h0 = __floats2half2_rn(ar[i][0].x, ar[i][0].y);
            __half2 h1 = __floats2half2_rn(ar[i][0].z, ar[i][0].w);
            __half2 h2 = __floats2half2_rn(ar[i][1].x, ar[i][1].y);
            __half2 h3 = __floats2half2_rn(ar[i][1].z, ar[i][1].w);
            t.x = *reinterpret_cast<uint32_t*>(&h0);
            t.y = *reinterpret_cast<uint32_t*>(&h1);
            t.z = *reinterpret_cast<uint32_t*>(&h2);
            t.w = *reinterpret_cast<uint32_t*>(&h3);
            *(uint4*)(base + ldOff[i]) = t;
        }
    };

    float4 ar[4][2];
    ldgA(0, ar);
    issueB(0);
    if (nc > 1) issueB(1);
    stsA(0, ar);
    if (nc > 1) ldgA(1, ar);

    for (int cidx = 0; cidx < nc; cidx++) {
        if (cidx + 1 < nc) cp_wait1(); else cp_wait0();
        __syncthreads();
        if (cidx + 2 < nc) issueB(cidx + 2);
        if (cidx + 1 < nc) stsA(cidx + 1, ar);
        if (cidx + 2 < nc) ldgA(cidx + 2, ar);
        const uint32_t st = sb + (uint32_t)(cidx % 3) * TG_STAGE;
        compute_chunk_f16(st, st + 16384u, aoff, boff, c);
    }
    __syncthreads();

    // epilogue
    float* sf = (float*)smem;
#pragma unroll
    for (int i = 0; i < 4; i++) {
        const int r = m0 + i * 16 + (lane >> 2);
#pragma unroll
        for (int j = 0; j < 4; j++) {
            const int cc = n0 + j * 8 + (lane & 3) * 2;
            sf[r * 136 + cc]           = c[i][j][0];
            sf[r * 136 + cc + 1]       = c[i][j][1];
            sf[(r + 8) * 136 + cc]     = c[i][j][2];
            sf[(r + 8) * 136 + cc + 1] = c[i][j][3];
        }
    }
    __syncthreads();
#pragma unroll 4
    for (int e = tid; e < 128 * 128; e += TG_THREADS) {
        int r, cc;
        if (transOut) { r = e & 127; cc = e >> 7; }   // r fast => coalesced trans store
        else          { r = e >> 7;  cc = e & 127; }
        float v = sf[r * 136 + cc] + bias[colBase + cc];
        long long gi;
        if (transOut) {
            const int grow = rowBase + r;
            gi = (long long)(grow >> 11) * ((long long)DD * SS)
               + (long long)(colBase + cc) * SS + (grow & 2047);
        } else {
            gi = (long long)(rowBase + r) * N + colBase + cc;
        }
        out[gi] = __float2half_rn(v);
    }
}

// ---------------------------------------------------------------------------
// fp32 SGEMM (small 512^3 fold GEMMs only): C = A @ B
// ---------------------------------------------------------------------------
__global__ __launch_bounds__(256)
void sgemm_nn_kernel(const float* __restrict__ A, const float* __restrict__ Bm,
                     float* __restrict__ C, int M, int N, int K)
{
    const int BK = 8;
    __shared__ float As[BK][128];
    __shared__ float Bs[BK][128];
    const int tid = threadIdx.x;
    const int tx = tid & 15, ty = tid >> 4;
    const int rowBase = blockIdx.y * 128, colBase = blockIdx.x * 128;
    float acc[8][8];
#pragma unroll
    for (int i = 0; i < 8; i++)
#pragma unroll
        for (int j = 0; j < 8; j++) acc[i][j] = 0.0f;

    for (int k0 = 0; k0 < K; k0 += BK) {
        {
            const int r = tid >> 1, kc = (tid & 1) * 4;
            float4 a = *reinterpret_cast<const float4*>(A + (long long)(rowBase + r) * K + k0 + kc);
            As[kc + 0][r] = a.x; As[kc + 1][r] = a.y; As[kc + 2][r] = a.z; As[kc + 3][r] = a.w;
        }
        {
            const int kr = tid >> 5, ccc = (tid & 31) * 4;
            float4 b = *reinterpret_cast<const float4*>(Bm + (long long)(k0 + kr) * N + colBase + ccc);
            Bs[kr][ccc + 0] = b.x; Bs[kr][ccc + 1] = b.y; Bs[kr][ccc + 2] = b.z; Bs[kr][ccc + 3] = b.w;
        }
        __syncthreads();
#pragma unroll
        for (int k = 0; k < BK; k++) {
            float4 a0 = *reinterpret_cast<const float4*>(&As[k][ty * 8]);
            float4 a1 = *reinterpret_cast<const float4*>(&As[k][ty * 8 + 4]);
            float4 b0 = *reinterpret_cast<const float4*>(&Bs[k][tx * 8]);
            float4 b1 = *reinterpret_cast<const float4*>(&Bs[k][tx * 8 + 4]);
            float arr[8] = {a0.x, a0.y, a0.z, a0.w, a1.x, a1.y, a1.z, a1.w};
            float brr[8] = {b0.x, b0.y, b0.z, b0.w, b1.x, b1.y, b1.z, b1.w};
#pragma unroll
            for (int i = 0; i < 8; i++)
#pragma unroll
                for (int j = 0; j < 8; j++) acc[i][j] = fmaf(arr[i], brr[j], acc[i][j]);
        }
        __syncthreads();
    }
#pragma unroll
    for (int i = 0; i < 8; i++) {
        const int r = rowBase + ty * 8 + i;
#pragma unroll
        for (int j = 0; j < 8; j += 4) {
            const int cc = colBase + tx * 8 + j;
            float4 v = {acc[i][j], acc[i][j + 1], acc[i][j + 2], acc[i][j + 3]};
            *reinterpret_cast<float4*>(C + (long long)r * N + cc) = v;
        }
    }
}

// merged: y=0 -> bkp = E1@bk ; y=1 -> bvp = E2@bv
__global__ void fuse_bias2_kernel(const float* __restrict__ E1,
                                  const float* __restrict__ E2,
                                  const float* __restrict__ bk,
                                  const float* __restrict__ bv,
                                  float* __restrict__ o1,
                                  float* __restrict__ o2)
{
    __shared__ float red[8];
    const float* E = blockIdx.y ? E2 : E1;
    const float* b = blockIdx.y ? bv : bk;
    float* o       = blockIdx.y ? o2 : o1;
    const int p = blockIdx.x;
    float s = 0.0f;
    for (int d = threadIdx.x; d < DD; d += 256)
        s = fmaf(E[(long long)p * DD + d], b[d], s);
#pragma unroll
    for (int off = 16; off > 0; off >>= 1) s += __shfl_xor_sync(0xffffffffu, s, off);
    if ((threadIdx.x & 31) == 0) red[threadIdx.x >> 5] = s;
    __syncthreads();
    if (threadIdx.x == 0) {
        float t = 0.0f;
#pragma unroll
        for (int i = 0; i < 8; i++) t += red[i];
        o[p] = t;
    }
}

// convert 4 weight matrices fp32 -> fp16
struct Cvt4Args {
    const float* src[4];
    __half* dst[4];
};
__global__ void cvt4_kernel(Cvt4Args ca)
{
    const int z = blockIdx.z;
    const float* x = ca.src[z];
    __half* y = ca.dst[z];
    const int n = DD * DD;
    for (int i = blockIdx.x * blockDim.x + threadIdx.x; i < n;
         i += gridDim.x * blockDim.x)
        y[i] = __float2half_rn(x[i]);
}

// softmax rows of 2048 in place (exact fp32) + fp16 copy
__global__ __launch_bounds__(256)
void softmax2048_kernel(float* __restrict__ data, __half* __restrict__ half_out)
{
    const size_t base = (size_t)blockIdx.x * 2048;
    float* row = data + base;
    const int tid = threadIdx.x;
    __shared__ float red[8];

    float v[8];
    float m = -3.4e38f;
#pragma unroll
    for (int i = 0; i < 8; i++) { v[i] = row[tid + 256 * i]; m = fmaxf(m, v[i]); }
#pragma unroll
    for (int o = 16; o > 0; o >>= 1) m = fmaxf(m, __shfl_xor_sync(0xffffffffu, m, o));
    if ((tid & 31) == 0) red[tid >> 5] = m;
    __syncthreads();
    float bm = red[0];
#pragma unroll
    for (int i = 1; i < 8; i++) bm = fmaxf(bm, red[i]);
    __syncthreads();

    float s = 0.0f;
#pragma unroll
    for (int i = 0; i < 8; i++) { v[i] = __expf(v[i] - bm); s += v[i]; }
#pragma unroll
    for (int o = 16; o > 0; o >>= 1) s += __shfl_xor_sync(0xffffffffu, s, o);
    if ((tid & 31) == 0) red[tid >> 5] = s;
    __syncthreads();
    float bs = 0.0f;
#pragma unroll
    for (int i = 0; i < 8; i++) bs += red[i];

    const float inv = 1.0f / bs;
#pragma unroll
    for (int i = 0; i < 8; i++) {
        float r = v[i] * inv;
        const size_t idx = base + tid + 256 * i;
        data[idx] = r;
        half_out[idx] = __float2half_rn(r);
    }
}

// ---------------------------------------------------------------------------
// Launch
// ---------------------------------------------------------------------------
extern "C" void kernel_launch(void* const* d_in, const int* in_sizes, int n_in,
                              void* d_out, int out_size)
{
    const float* q_in = (const float*)d_in[0];
    const float* k_in = (const float*)d_in[1];
    const float* v_in = (const float*)d_in[2];
    const float* Wq   = (const float*)d_in[3];
    const float* bq   = (const float*)d_in[4];
    const float* Wk   = (const float*)d_in[5];
    const float* bk   = (const float*)d_in[6];
    const float* Wv   = (const float*)d_in[7];
    const float* bv   = (const float*)d_in[8];
    const float* E1   = (const float*)d_in[9];
    const float* E2   = (const float*)d_in[10];
    const float* Wo   = (const float*)d_in[11];
    const float* bo   = (const float*)d_in[12];

    float* outp = (float*)d_out;
    float* attn = outp + (size_t)BB * SS * DD;

    float *p_Wkp, *p_Wvp, *p_bkp, *p_bvp;
    __half *wq_h, *wkp_h, *wvp_h, *wo_h;
    __half *p_q, *p_kp, *p_vpT, *p_op, *p_ath;
    cudaGetSymbolAddress((void**)&p_Wkp, g_Wkp);
    cudaGetSymbolAddress((void**)&p_Wvp, g_Wvp);
    cudaGetSymbolAddress((void**)&p_bkp, g_bkp);
    cudaGetSymbolAddress((void**)&p_bvp, g_bvp);
    cudaGetSymbolAddress((void**)&wq_h,  g_Wq_h);
    cudaGetSymbolAddress((void**)&wkp_h, g_Wkp_h);
    cudaGetSymbolAddress((void**)&wvp_h, g_Wvp_h);
    cudaGetSymbolAddress((void**)&wo_h,  g_Wo_h);
    cudaGetSymbolAddress((void**)&p_q,   g_q_h);
    cudaGetSymbolAddress((void**)&p_kp,  g_kp_h);
    cudaGetSymbolAddress((void**)&p_vpT, g_vpT_h);
    cudaGetSymbolAddress((void**)&p_op,  g_op_h);
    cudaGetSymbolAddress((void**)&p_ath, g_attn_h);

    cudaFuncSetAttribute(tgemm_f16_kernel, cudaFuncAttributeMaxDynamicSharedMemorySize, TG_SMEM);
    cudaFuncSetAttribute(tgemm_proj_kernel, cudaFuncAttributeMaxDynamicSharedMemorySize, TG_SMEM);

    const int M = BB * SS;
    const float scaling = 1.0f / sqrtf((float)DD);
    const dim3 gFold(DD / 128, DD / 128, 1);

    // 0,1: fold GEMMs (fp32 exact)
    sgemm_nn_kernel<<<gFold, 256>>>(E1, Wk, p_Wkp, DD, DD, DD);
    sgemm_nn_kernel<<<gFold, 256>>>(E2, Wv, p_Wvp, DD, DD, DD);
    // 2: folded biases
    fuse_bias2_kernel<<<dim3(DD, 2), 256>>>(E1, E2, bk, bv, p_bkp, p_bvp);
    // 3: convert 4 weight matrices to fp16
    {
        Cvt4Args ca;
        ca.src[0] = Wq;    ca.dst[0] = wq_h;
        ca.src[1] = p_Wkp; ca.dst[1] = wkp_h;
        ca.src[2] = p_Wvp; ca.dst[2] = wvp_h;
        ca.src[3] = Wo;    ca.dst[3] = wo_h;
        cvt4_kernel<<<dim3(128, 1, 4), 256>>>(ca);
    }
    // 4: merged q/k/v projections (grid.z = 3); v writes vpT
    {
        ProjArgs pa;
        pa.A[0] = q_in; pa.Bh[0] = wq_h;  pa.out[0] = p_q;   pa.bias[0] = bq;    pa.trans[0] = 0;
        pa.A[1] = k_in; pa.Bh[1] = wkp_h; pa.out[1] = p_kp;  pa.bias[1] = p_bkp; pa.trans[1] = 0;
        pa.A[2] = v_in; pa.Bh[2] = wvp_h; pa.out[2] = p_vpT; pa.bias[2] = p_bvp; pa.trans[2] = 1;
        tgemm_proj_kernel<<<dim3(DD / 128, M / 128, 3), TG_THREADS, TG_SMEM>>>(pa, M, DD, DD);
    }
    // 5: scores = scaling * q @ kp^T -> attn region (fp32)  [ncu target]
    tgemm_f16_kernel<<<dim3(SS / 128, SS / 128, BB), TG_THREADS, TG_SMEM>>>(
        p_q, p_kp, attn, nullptr, nullptr, SS, SS, DD, scaling,
        (long long)SS * DD, (long long)SS * DD, (long long)SS * SS);
    // 6: softmax in place + fp16 copy
    softmax2048_kernel<<<BB * SS, 256>>>(attn, p_ath);
    // 7: op = attn @ vpT^T (K = 2048) -> fp16
    tgemm_f16_kernel<<<dim3(DD / 128, SS / 128, BB), TG_THREADS, TG_SMEM>>>(
        p_ath, p_vpT, nullptr, p_op, nullptr, SS, DD, SS, 1.0f,
        (long long)SS * SS, (long long)SS * DD, (long long)SS * DD);
    // 8: out = op @ Wo^T + bo (fp32)
    tgemm_f16_kernel<<<dim3(DD / 128, M / 128, 1), TG_THREADS, TG_SMEM>>>(
        p_op, wo_h, outp, nullptr, bo, M, DD, DD, 1.0f, 0, 0, 0);
}